// round 7
// baseline (speedup 1.0000x reference)
#include <cuda_runtime.h>
#include <cuda_bf16.h>
#include <cstdint>

// ---------------------------------------------------------------------------
// PhaseFieldPredictor, round 6: same packed-FFMA2 / 2-nodes-per-thread math
// as round 5, but 128-thread CTAs (2x grid) so 3 CTAs/SM stay resident and
// the CLC backfill scheduler balances the tail. Targets the 16% wave tail +
// latency bubbles seen at 1.73 CTAs/SM.
// ---------------------------------------------------------------------------

#define NPLANE 65536            // 256*256
#define BN     131072           // 2 * 65536
#define WIDTH  64
typedef unsigned long long ull;

__device__ float g_feats[2 * WIDTH * NPLANE];   // 33.5 MB
__device__ float g_tf   [2 * WIDTH * NPLANE];   // 33.5 MB

__device__ __forceinline__ void ffma2(ull& acc, ull a, ull b) {
    asm("fma.rn.f32x2 %0, %1, %2, %0;" : "+l"(acc) : "l"(a), "l"(b));
}
__device__ __forceinline__ ull pk(float lo, float hi) {
    ull r; asm("mov.b64 %0, {%1, %2};" : "=l"(r) : "f"(lo), "f"(hi)); return r;
}
__device__ __forceinline__ float red2(ull v) {
    float lo, hi; asm("mov.b64 {%0, %1}, %2;" : "=f"(lo), "=f"(hi) : "l"(v));
    return lo + hi;
}
// one LDS.128 -> two packed-f32x2 weight pairs (saddr 16B aligned)
__device__ __forceinline__ void lds_w2(ull& w0, ull& w1, uint32_t saddr) {
    asm("ld.shared.v2.b64 {%0, %1}, [%2];" : "=l"(w0), "=l"(w1) : "r"(saddr));
}

__device__ __forceinline__ float fsig(float x) {
    return __fdividef(1.f, 1.f + __expf(-x));
}
__device__ __forceinline__ float ftanh(float x) {
    x = fminf(fmaxf(x, -15.f), 15.f);
    float e = __expf(2.f * x);
    return __fdividef(e - 1.f, e + 1.f);
}

// 2-node packed dot: one weight load feeds 4 FFMA2.
template<int NPAIR>
__device__ __forceinline__ void dot4(ull& aA0, ull& aA1, ull& aB0, ull& aB1,
                                     uint32_t waddr,
                                     const ull* __restrict__ vA,
                                     const ull* __restrict__ vB)
{
    #pragma unroll
    for (int p = 0; p < NPAIR / 2; p++) {
        ull w0, w1;
        lds_w2(w0, w1, waddr + p * 16);
        ffma2(aA0, vA[2 * p],     w0);
        ffma2(aB0, vB[2 * p],     w0);
        ffma2(aA1, vA[2 * p + 1], w1);
        ffma2(aB1, vB[2 * p + 1], w1);
    }
}

// ---------------------------------------------------------------------------
// Shared layout (float units) -- weights only, 66KB -> 3 CTAs/SM resident.
// ---------------------------------------------------------------------------
#define OFF_WIH0  0        // 128 rows * 12 (10 data + 2 zero pad)
#define OFF_WHH0  1536     // 128*32
#define OFF_WIH1  5632     // 128*32
#define OFF_WHH1  9728     // 128*32
#define OFF_B0    13824    // 128 ull packed {bias,0} = 256 floats
#define OFF_B1    14080    // 256
#define OFF_FC1W  14336    // 64*32
#define OFF_FC1B  16384    // 64 ull = 128 floats
#define LSTM_SMEM_FLOATS 16512
#define LSTM_SMEM_BYTES  (LSTM_SMEM_FLOATS * 4)   // 66 KB

// One LSTM cell for a node pair. XPAIR = input pairs, WSTB = Wih row bytes.
// Gate order (torch): rows [0:32)=i, [32:64)=f, [64:96)=g, [96:128)=o.
template<int XPAIR, int WSTB>
__device__ __forceinline__ void cell2(
    const ull* __restrict__ xA, const ull* __restrict__ xB,
    ull* __restrict__ hA, ull* __restrict__ hB,
    float* __restrict__ cA, float* __restrict__ cB,        // local [32]
    float* __restrict__ hnA, float* __restrict__ hnB,      // local [32]
    uint32_t aWih, uint32_t aWhh, const ull* __restrict__ Bp)
{
    #pragma unroll 1
    for (int j = 0; j < 32; j++) {
        float zA[4], zB[4];
        #pragma unroll
        for (int g = 0; g < 4; g++) {
            ull b = Bp[g * 32 + j];
            ull aA0 = b, aA1 = 0ull, aB0 = b, aB1 = 0ull;
            dot4<XPAIR>(aA0, aA1, aB0, aB1, aWih + (g * 32 + j) * WSTB, xA, xB);
            dot4<16>(aA0, aA1, aB0, aB1, aWhh + (g * 32 + j) * 128, hA, hB);
            zA[g] = red2(aA0) + red2(aA1);
            zB[g] = red2(aB0) + red2(aB1);
        }
        float cv = cA[j];
        cv = fsig(zA[1]) * cv + fsig(zA[0]) * ftanh(zA[2]);
        cA[j] = cv;
        hnA[j] = fsig(zA[3]) * ftanh(cv);

        cv = cB[j];
        cv = fsig(zB[1]) * cv + fsig(zB[0]) * ftanh(zB[2]);
        cB[j] = cv;
        hnB[j] = fsig(zB[3]) * ftanh(cv);
    }
    #pragma unroll
    for (int k = 0; k < 16; k++) {
        hA[k] = pk(hnA[2 * k], hnA[2 * k + 1]);
        hB[k] = pk(hnB[2 * k], hnB[2 * k + 1]);
    }
}

__global__ __launch_bounds__(128) void lstm_kernel(
    const float* __restrict__ x,
    const float* __restrict__ Wih0, const float* __restrict__ Whh0,
    const float* __restrict__ bih0, const float* __restrict__ bhh0,
    const float* __restrict__ Wih1, const float* __restrict__ Whh1,
    const float* __restrict__ bih1, const float* __restrict__ bhh1,
    const float* __restrict__ fc1w, const float* __restrict__ fc1b)
{
    extern __shared__ float sm[];
    int tid = threadIdx.x;

    for (int i = tid; i < 128 * 12; i += 128) {
        int r = i / 12, col = i % 12;
        sm[OFF_WIH0 + i] = (col < 10) ? Wih0[r * 10 + col] : 0.f;
    }
    for (int i = tid; i < 128 * 32; i += 128) {
        sm[OFF_WHH0 + i] = Whh0[i];
        sm[OFF_WIH1 + i] = Wih1[i];
        sm[OFF_WHH1 + i] = Whh1[i];
    }
    if (tid < 128) {
        reinterpret_cast<ull*>(&sm[OFF_B0])[tid] = pk(bih0[tid] + bhh0[tid], 0.f);
        reinterpret_cast<ull*>(&sm[OFF_B1])[tid] = pk(bih1[tid] + bhh1[tid], 0.f);
    }
    for (int i = tid; i < 64 * 32; i += 128) sm[OFF_FC1W + i] = fc1w[i];
    if (tid < 64)
        reinterpret_cast<ull*>(&sm[OFF_FC1B])[tid] = pk(fc1b[tid], 0.f);
    __syncthreads();

    int pairid = blockIdx.x * 128 + tid;         // 0..65535
    int b = pairid >> 15;
    int n0 = (pairid & 32767) * 2;
    const float* xb = x + (size_t)b * 50 * NPLANE + n0;

    uint32_t sbase = (uint32_t)__cvta_generic_to_shared(sm);
    uint32_t aW0i = sbase + OFF_WIH0 * 4;
    uint32_t aW0h = sbase + OFF_WHH0 * 4;
    uint32_t aW1i = sbase + OFF_WIH1 * 4;
    uint32_t aW1h = sbase + OFF_WHH1 * 4;
    const ull* B0 = reinterpret_cast<const ull*>(&sm[OFF_B0]);
    const ull* B1 = reinterpret_cast<const ull*>(&sm[OFF_B1]);

    // per-thread state: h packed in registers, c / h-new staging in local
    ull h0A[16], h0B[16], h1A[16], h1B[16];
    #pragma unroll
    for (int k = 0; k < 16; k++) {
        h0A[k] = 0ull; h0B[k] = 0ull; h1A[k] = 0ull; h1B[k] = 0ull;
    }
    float cA0[32], cB0[32], cA1[32], cB1[32], hnA[32], hnB[32];
    #pragma unroll
    for (int k = 0; k < 32; k++) {
        cA0[k] = 0.f; cB0[k] = 0.f; cA1[k] = 0.f; cB1[k] = 0.f;
    }

    for (int t = 0; t < 5; t++) {
        float2 v[10];
        #pragma unroll
        for (int c = 0; c < 10; c++)
            v[c] = *reinterpret_cast<const float2*>(xb + ((size_t)(t * 10 + c) << 16));
        ull xA[6], xB[6];
        #pragma unroll
        for (int k = 0; k < 5; k++) {
            xA[k] = pk(v[2 * k].x, v[2 * k + 1].x);
            xB[k] = pk(v[2 * k].y, v[2 * k + 1].y);
        }
        xA[5] = 0ull; xB[5] = 0ull;    // matches zero-padded weight cols 10,11

        cell2<6, 48>(xA, xB, h0A, h0B, cA0, cB0, hnA, hnB, aW0i, aW0h, B0);
        cell2<16, 128>(h0A, h0B, h1A, h1B, cA1, cB1, hnA, hnB, aW1i, aW1h, B1);
    }

    // fused fc1 + relu -> feats (channel-major), float2 per pair
    uint32_t aF1 = sbase + OFF_FC1W * 4;
    const ull* FB = reinterpret_cast<const ull*>(&sm[OFF_FC1B]);
    float* fo = g_feats + ((size_t)b * WIDTH << 16) + n0;
    #pragma unroll 1
    for (int j = 0; j < WIDTH; j++) {
        ull bj = FB[j];
        ull aA0 = bj, aA1 = 0ull, aB0 = bj, aB1 = 0ull;
        dot4<16>(aA0, aA1, aB0, aB1, aF1 + j * 128, h1A, h1B);
        float2 r;
        r.x = fmaxf(red2(aA0) + red2(aA1), 0.f);
        r.y = fmaxf(red2(aB0) + red2(aB1), 0.f);
        *reinterpret_cast<float2*>(fo + ((size_t)j << 16)) = r;
    }
}

// ---------------------------------------------------------------------------
// Graph conv step A: tf = feats @ W, 2 nodes/thread, transposed weights.
// 128-thread CTAs for residency/backfill.
// ---------------------------------------------------------------------------
__global__ __launch_bounds__(128) void gconv_gemm_kernel(const float* __restrict__ W)
{
    __shared__ __align__(16) float sWT[64 * 64];
    int tid = threadIdx.x;
    for (int idx = tid; idx < 4096; idx += 128) {
        int j = idx >> 6, i = idx & 63;
        sWT[idx] = W[i * 64 + j];
    }
    __syncthreads();

    int pairid = blockIdx.x * 128 + tid;     // 0..65535
    int b = pairid >> 15;
    int n0 = (pairid & 32767) * 2;
    const float* f = g_feats + ((size_t)b * WIDTH << 16) + n0;

    ull xA[32], xB[32];
    #pragma unroll
    for (int k = 0; k < 32; k++) {
        float2 v0 = *reinterpret_cast<const float2*>(f + ((size_t)(2 * k) << 16));
        float2 v1 = *reinterpret_cast<const float2*>(f + ((size_t)(2 * k + 1) << 16));
        xA[k] = pk(v0.x, v1.x);
        xB[k] = pk(v0.y, v1.y);
    }

    uint32_t aW = (uint32_t)__cvta_generic_to_shared(sWT);
    float* o = g_tf + ((size_t)b * WIDTH << 16) + n0;
    #pragma unroll 2
    for (int j = 0; j < WIDTH; j++) {
        ull aA0 = 0ull, aA1 = 0ull, aB0 = 0ull, aB1 = 0ull;
        dot4<32>(aA0, aA1, aB0, aB1, aW + j * 256, xA, xB);
        float2 r;
        r.x = red2(aA0) + red2(aA1);
        r.y = red2(aB0) + red2(aB1);
        *reinterpret_cast<float2*>(o + ((size_t)j << 16)) = r;
    }
}

// ---------------------------------------------------------------------------
// Graph conv step B: 8-neighbor gaussian stencil, float4 vectorized.
// ---------------------------------------------------------------------------
__global__ __launch_bounds__(256) void gconv_stencil_kernel(
    const float* __restrict__ convb, const float* __restrict__ gparam,
    int layer, int dorelu)
{
    int idx4 = blockIdx.x * 256 + threadIdx.x;   // float4 id
    int n4 = idx4 & 16383;
    int p = idx4 >> 14;                          // b*64 + c
    int c = p & 63;
    int i = n4 >> 6;
    int q = n4 & 63;
    int n = n4 << 2;

    float g = gparam[layer];
    float inv = __fdividef(1.f, g * g + 1e-8f);
    float gax = __expf(-inv);
    float gdi = __expf(-2.f * inv);

    const float* tf = g_tf + ((size_t)p << 16);
    const float4* tf4 = reinterpret_cast<const float4*>(tf);

    bool up = (i > 0), dn = (i < 255), lf = (q > 0), rt = (q < 63);

    float4 cm = tf4[n4];
    float4 um = up ? tf4[n4 - 64] : make_float4(0, 0, 0, 0);
    float4 dm = dn ? tf4[n4 + 64] : make_float4(0, 0, 0, 0);
    float clf = lf ? tf[n - 1]   : 0.f;
    float crt = rt ? tf[n + 4]   : 0.f;
    float ulf = (up && lf) ? tf[n - 257] : 0.f;
    float urt = (up && rt) ? tf[n - 252] : 0.f;
    float dlf = (dn && lf) ? tf[n + 255] : 0.f;
    float drt = (dn && rt) ? tf[n + 260] : 0.f;

    float bias = convb[c];

    float4 r;
    r.x = cm.x + gax * (clf  + cm.y + um.x + dm.x) + gdi * (ulf  + um.y + dlf  + dm.y) + bias;
    r.y = cm.y + gax * (cm.x + cm.z + um.y + dm.y) + gdi * (um.x + um.z + dm.x + dm.z) + bias;
    r.z = cm.z + gax * (cm.y + cm.w + um.z + dm.z) + gdi * (um.y + um.w + dm.y + dm.w) + bias;
    r.w = cm.w + gax * (cm.z + crt  + um.w + dm.w) + gdi * (um.z + urt  + dm.z + drt ) + bias;

    if (dorelu) {
        r.x = fmaxf(r.x, 0.f); r.y = fmaxf(r.y, 0.f);
        r.z = fmaxf(r.z, 0.f); r.w = fmaxf(r.w, 0.f);
    }
    reinterpret_cast<float4*>(g_feats)[idx4] = r;
}

// ---------------------------------------------------------------------------
// Head: out = relu(feats @ fc2^T + b2) @ fc3^T + b3, 2 nodes/thread.
// ---------------------------------------------------------------------------
__global__ __launch_bounds__(128) void head_kernel(
    const float* __restrict__ fc2w, const float* __restrict__ fc2b,
    const float* __restrict__ fc3w, const float* __restrict__ fc3b,
    float* __restrict__ out)
{
    __shared__ __align__(16) float s2w[32 * 64];
    __shared__ __align__(16) float s3w[10 * 32];
    __shared__ float s2b[32];
    __shared__ float s3b[16];
    int tid = threadIdx.x;
    for (int i = tid; i < 32 * 64; i += 128) s2w[i] = fc2w[i];
    for (int i = tid; i < 10 * 32; i += 128) s3w[i] = fc3w[i];
    if (tid < 32) s2b[tid] = fc2b[tid];
    if (tid < 10) s3b[tid] = fc3b[tid];
    __syncthreads();

    int pairid = blockIdx.x * 128 + tid;     // 0..65535
    int b = pairid >> 15;
    int n0 = (pairid & 32767) * 2;
    const float* f = g_feats + ((size_t)b * WIDTH << 16) + n0;

    ull fA[32], fB[32];
    #pragma unroll
    for (int k = 0; k < 32; k++) {
        float2 v0 = *reinterpret_cast<const float2*>(f + ((size_t)(2 * k) << 16));
        float2 v1 = *reinterpret_cast<const float2*>(f + ((size_t)(2 * k + 1) << 16));
        fA[k] = pk(v0.x, v1.x);
        fB[k] = pk(v0.y, v1.y);
    }

    uint32_t a2 = (uint32_t)__cvta_generic_to_shared(s2w);
    uint32_t a3 = (uint32_t)__cvta_generic_to_shared(s3w);

    float yA[32], yB[32];                    // local staging
    #pragma unroll 1
    for (int p = 0; p < 32; p++) {
        ull aA0 = 0ull, aA1 = 0ull, aB0 = 0ull, aB1 = 0ull;
        dot4<32>(aA0, aA1, aB0, aB1, a2 + p * 256, fA, fB);
        yA[p] = fmaxf(s2b[p] + red2(aA0) + red2(aA1), 0.f);
        yB[p] = fmaxf(s2b[p] + red2(aB0) + red2(aB1), 0.f);
    }
    ull yAp[16], yBp[16];
    #pragma unroll
    for (int k = 0; k < 16; k++) {
        yAp[k] = pk(yA[2 * k], yA[2 * k + 1]);
        yBp[k] = pk(yB[2 * k], yB[2 * k + 1]);
    }

    #pragma unroll
    for (int oc = 0; oc < 10; oc++) {
        ull aA0 = 0ull, aA1 = 0ull, aB0 = 0ull, aB1 = 0ull;
        dot4<16>(aA0, aA1, aB0, aB1, a3 + oc * 128, yAp, yBp);
        float2 r;
        r.x = s3b[oc] + red2(aA0) + red2(aA1);
        r.y = s3b[oc] + red2(aB0) + red2(aB1);
        *reinterpret_cast<float2*>(out + (((size_t)(b * 10 + oc)) << 16) + n0) = r;
    }
}

// ---------------------------------------------------------------------------
// Host launch
// ---------------------------------------------------------------------------
extern "C" void kernel_launch(void* const* d_in, const int* in_sizes, int n_in,
                              void* d_out, int out_size)
{
    const float* x     = (const float*)d_in[0];
    // d_in[1..3]: edge lists — fixed 8-neighbor grid, implemented as stencil.
    const float* Wih0  = (const float*)d_in[4];
    const float* Whh0  = (const float*)d_in[5];
    const float* bih0  = (const float*)d_in[6];
    const float* bhh0  = (const float*)d_in[7];
    const float* Wih1  = (const float*)d_in[8];
    const float* Whh1  = (const float*)d_in[9];
    const float* bih1  = (const float*)d_in[10];
    const float* bhh1  = (const float*)d_in[11];
    const float* fc1w  = (const float*)d_in[12];
    const float* fc1b  = (const float*)d_in[13];
    const float* convw = (const float*)d_in[14];
    const float* convb = (const float*)d_in[15];
    const float* gparam= (const float*)d_in[16];
    const float* fc2w  = (const float*)d_in[17];
    const float* fc2b  = (const float*)d_in[18];
    const float* fc3w  = (const float*)d_in[19];
    const float* fc3b  = (const float*)d_in[20];
    float* out = (float*)d_out;

    cudaFuncSetAttribute(lstm_kernel,
                         cudaFuncAttributeMaxDynamicSharedMemorySize,
                         LSTM_SMEM_BYTES);

    // 65536 node pairs, 128 threads/CTA -> 512 CTAs (3 resident/SM, backfill)
    lstm_kernel<<<512, 128, LSTM_SMEM_BYTES>>>(
        x, Wih0, Whh0, bih0, bhh0, Wih1, Whh1, bih1, bhh1, fc1w, fc1b);

    for (int k = 0; k < 4; k++) {
        gconv_gemm_kernel<<<512, 128>>>(convw + (size_t)k * 64 * 64);
        gconv_stencil_kernel<<<(2 * WIDTH * NPLANE / 4) / 256, 256>>>(
            convb + (size_t)k * 64, gparam, k, (k != 3) ? 1 : 0);
    }

    head_kernel<<<512, 128>>>(fc2w, fc2b, fc3w, fc3b, out);
}